// round 12
// baseline (speedup 1.0000x reference)
#include <cuda_runtime.h>
#include <cstdint>

namespace {

constexpr int Bn = 256, Dn = 256, Nn = 1024;
constexpr int CL = 8;          // cluster size (CTAs per batch)
constexpr int TPB = 512;
constexpr int SL = 128;        // n-columns per CTA slice
constexpr float EPS_NORM = 1e-12f;
constexpr float EPS_DIV  = 1e-5f;

// dynamic smem layout (float offsets)
constexpr int OFF_XS  = 0;                   // 256*128 x-slice
constexpr int OFF_ZP  = 32768;               // 2 * 264 (z partial + 2 scalars, dbl buf)
constexpr int OFF_ZF  = OFF_ZP + 528;        // 260 allreduced z + scalars
constexpr int OFF_V   = OFF_ZF + 260;        // 256
constexpr int OFF_V1  = OFF_V + 256;         // 256
constexpr int OFF_U1  = OFF_V1 + 256;        // 128 (local slice)
constexpr int OFF_U2  = OFF_U1 + 128;        // 128
constexpr int OFF_WL  = OFF_U2 + 128;        // 128
constexpr int OFF_WP  = OFF_WL + 128;        // 8*128 w partials
constexpr int OFF_RED = OFF_WP + 1024;       // 16
constexpr int OFF_SS  = OFF_RED + 16;        // 2
constexpr int SMEM_BYTES = (OFF_SS + 4) * 4; // ~142 KB

__device__ __forceinline__ unsigned cluster_rank() {
    unsigned r;
    asm("mov.u32 %0, %%cluster_ctarank;" : "=r"(r));
    return r;
}

__device__ __forceinline__ void cluster_sync() {
    asm volatile("barrier.cluster.arrive.aligned;" ::: "memory");
    asm volatile("barrier.cluster.wait.aligned;" ::: "memory");
}

// Block-wide sum over 512 threads (16 warps). All threads must call.
__device__ __forceinline__ float block_reduce(float val, float* red) {
#pragma unroll
    for (int o = 16; o; o >>= 1) val += __shfl_down_sync(0xffffffffu, val, o);
    const int lane = threadIdx.x & 31;
    const int w    = threadIdx.x >> 5;
    if (lane == 0) red[w] = val;
    __syncthreads();
    if (w == 0) {
        val = (lane < 16) ? red[lane] : 0.f;
#pragma unroll
        for (int o = 8; o; o >>= 1) val += __shfl_down_sync(0xffffffffu, val, o);
        if (lane == 0) red[0] = val;
    }
    __syncthreads();
    float r = red[0];
    __syncthreads();
    return r;
}

__global__ __launch_bounds__(TPB, 1) __cluster_dims__(CL, 1, 1)
void svpn_kernel(const float* __restrict__ x,       // (B, D, N)
                 const float* __restrict__ weight,  // (D,)
                 float* __restrict__ out)           // (B, D*N)
{
    extern __shared__ float sm[];
    __shared__ __align__(8) unsigned long long mbar;

    float* xs  = sm + OFF_XS;
    float* zp  = sm + OFF_ZP;
    float* zf  = sm + OFF_ZF;
    float* vv  = sm + OFF_V;
    float* v1  = sm + OFF_V1;
    float* u1l = sm + OFF_U1;
    float* u2l = sm + OFF_U2;
    float* wl  = sm + OFF_WL;
    float* wp  = sm + OFF_WP;
    float* red = sm + OFF_RED;
    float* sS  = sm + OFF_SS;

    const int tid = threadIdx.x;
    const unsigned rank = cluster_rank();          // 0..7
    const int b  = blockIdx.x / CL;
    const int n0 = (int)rank * SL;
    const float* xb = x + (size_t)b * (Dn * Nn);

    const unsigned mb = (unsigned)__cvta_generic_to_shared(&mbar);

    if (tid == 0)
        asm volatile("mbarrier.init.shared.b64 [%0], 1;" :: "r"(mb) : "memory");
    __syncthreads();
    if (tid == 0)
        asm volatile("mbarrier.arrive.expect_tx.shared.b64 _, [%0], %1;"
                     :: "r"(mb), "r"(SL * Dn * 4) : "memory");
    __syncthreads();

    // load x slice: 256 rows x 512B, one bulk op per row (threads 0..255)
    if (tid < Dn) {
        unsigned dst = (unsigned)__cvta_generic_to_shared(xs + tid * SL);
        const float* src = xb + (size_t)tid * Nn + n0;
        asm volatile(
            "cp.async.bulk.shared::cluster.global.mbarrier::complete_tx::bytes "
            "[%0], [%1], %2, [%3];"
            :: "r"(dst), "l"(src), "r"(SL * 4), "r"(mb) : "memory");
    }
    if (tid < Dn) vv[tid] = weight[tid];

    // wait for load (phase 0)
    asm volatile(
        "{\n\t.reg .pred P1;\n\t"
        "WL%=:\n\t"
        "mbarrier.try_wait.parity.acquire.cta.shared::cta.b64 P1, [%0], 0, 0x989680;\n\t"
        "@P1 bra.uni WD%=;\n\t"
        "bra.uni WL%=;\n\t"
        "WD%=:\n\t}"
        :: "r"(mb) : "memory");
    __syncthreads();

    const int g    = tid >> 6;   // 0..7 : d-group of 32 rows (w-phase)
    const int p    = tid & 63;   // float2 column index   (w-phase)
    const int wid_ = tid >> 5, lane = tid & 31;
    const float2* xs2 = reinterpret_cast<const float2*>(xs);
    const float4* xs4 = reinterpret_cast<const float4*>(xs);
    const float4* wl4 = reinterpret_cast<const float4*>(wl);

    float s1 = 0.f;

    for (int sv = 0; sv < 2; ++sv) {
        for (int it = 0; it < 3; ++it) {
            const int buf = (((sv * 3 + it) & 1) ? 264 : 0);

            // replicated deflation scalar c_u = s1 * (v1 . v)
            float c_u = 0.f;
            if (sv) {
                float pr = (tid < Dn) ? v1[tid] * vv[tid] : 0.f;
                c_u = s1 * block_reduce(pr, red);
            }

            // ---- w-phase: partial w over 32 d's per group (float2 columns) ----
            float vreg[32];
#pragma unroll
            for (int i = 0; i < 32; ++i) vreg[i] = vv[g * 32 + i];
            float2 acc = make_float2(0.f, 0.f);
#pragma unroll
            for (int i = 0; i < 32; ++i) {
                float2 xv = xs2[(g * 32 + i) * 64 + p];
                acc.x = fmaf(xv.x, vreg[i], acc.x);
                acc.y = fmaf(xv.y, vreg[i], acc.y);
            }
            reinterpret_cast<float2*>(wp)[g * 64 + p] = acc;
            __syncthreads();

            if (tid < 64) {
                float2 w = make_float2(0.f, 0.f);
#pragma unroll
                for (int gg = 0; gg < 8; ++gg) {
                    float2 t = reinterpret_cast<const float2*>(wp)[gg * 64 + tid];
                    w.x += t.x; w.y += t.y;
                }
                if (sv) {
                    float2 uu = reinterpret_cast<const float2*>(u1l)[tid];
                    w.x -= c_u * uu.x; w.y -= c_u * uu.y;
                }
                reinterpret_cast<float2*>(wl)[tid] = w;
            }
            __syncthreads();

            // ---- local scalar partials ----
            float wv_  = (tid < SL) ? wl[tid] : 0.f;
            float sw2p = block_reduce(wv_ * wv_, red);
            float su1p = 0.f;
            if (sv) su1p = block_reduce((tid < SL) ? u1l[tid] * wv_ : 0.f, red);

            // ---- z partials: warp per row, float4 ----
#pragma unroll 4
            for (int k = 0; k < 16; ++k) {
                const int d = wid_ * 16 + k;
                float4 xv  = xs4[d * 32 + lane];
                float4 wv4 = wl4[lane];
                float r_ = fmaf(xv.x, wv4.x,
                           fmaf(xv.y, wv4.y,
                           fmaf(xv.z, wv4.z, xv.w * wv4.w)));
#pragma unroll
                for (int o = 16; o; o >>= 1)
                    r_ += __shfl_down_sync(0xffffffffu, r_, o);
                if (lane == 0) zp[buf + d] = r_;
            }
            if (tid == 0) { zp[buf + 256] = sw2p; zp[buf + 257] = su1p; }

            cluster_sync();

            // ---- DSMEM allreduce of 258 floats across the 8 CTAs ----
            if (tid < 258) {
                unsigned base =
                    (unsigned)__cvta_generic_to_shared(zp + buf) + (unsigned)tid * 4u;
                float a = 0.f;
#pragma unroll
                for (int r = 0; r < CL; ++r) {
                    unsigned pa;
                    asm("mapa.shared::cluster.u32 %0, %1, %2;"
                        : "=r"(pa) : "r"(base), "r"(r));
                    float v_;
                    asm("ld.shared::cluster.f32 %0, [%1];" : "=f"(v_) : "r"(pa));
                    a += v_;
                }
                zf[tid] = a;
            }
            __syncthreads();

            const float sw2  = zf[256];
            const float su1w = zf[257];
            float zd = 0.f;
            if (tid < Dn) {
                zd = zf[tid];
                if (sv) zd -= s1 * su1w * v1[tid];
            }
            float zz = block_reduce((tid < Dn) ? zd * zd : 0.f, red);
            float nz = sqrtf(zz);
            if (tid < Dn) vv[tid] = zd / fmaxf(nz, EPS_NORM);

            if (it == 2) {
                float nw   = fmaxf(sqrtf(sw2), EPS_NORM);
                float invw = 1.f / nw;
                float sval = nz / nw;                 // s = ||A^T u||
                if (sv == 0) {
                    if (tid < SL) u1l[tid] = wl[tid] * invw;
                    if (tid < Dn) v1[tid]  = zd / fmaxf(nz, EPS_NORM);
                    if (tid == 0) sS[0] = sval;
                } else {
                    if (tid < SL) u2l[tid] = wl[tid] * invw;
                    if (tid == 0) sS[1] = sval;
                }
            }
            __syncthreads();
        }
        if (sv == 0) {
            s1 = sS[0];
            if (tid < Dn) vv[tid] = weight[tid];
            __syncthreads();
        }
    }

    // ---- epilogue: out = c*x + c1*u1 v1^T + c2*u2 v2^T  (in-place in smem) ----
    const float s1f = sS[0], s2f = sS[1];
    const float c  = 1.f / (sqrtf(s2f) + EPS_DIV);
    const float c1 = sqrtf(s1f) - s1f * c;
    const float c2 = sqrtf(s2f) - s2f * c;

    float4* xw = reinterpret_cast<float4*>(xs);
    const float4* u14 = reinterpret_cast<const float4*>(u1l);
    const float4* u24 = reinterpret_cast<const float4*>(u2l);
#pragma unroll
    for (int k = 0; k < 16; ++k) {
        const int idx  = tid + k * TPB;      // 0..8191 (256 rows x 32 float4)
        const int d    = idx >> 5;
        const int col4 = idx & 31;
        const float a1 = c1 * v1[d];
        const float a2 = c2 * vv[d];        // vv holds v2
        float4 xv = xw[idx];
        float4 uA = u14[col4];
        float4 uB = u24[col4];
        float4 o;
        o.x = fmaf(c, xv.x, fmaf(a1, uA.x, a2 * uB.x));
        o.y = fmaf(c, xv.y, fmaf(a1, uA.y, a2 * uB.y));
        o.z = fmaf(c, xv.z, fmaf(a1, uA.z, a2 * uB.z));
        o.w = fmaf(c, xv.w, fmaf(a1, uA.w, a2 * uB.w));
        xw[idx] = o;
    }
    __syncthreads();
    asm volatile("fence.proxy.async.shared::cta;" ::: "memory");

    if (tid < Dn) {
        unsigned src = (unsigned)__cvta_generic_to_shared(xs + tid * SL);
        float* dst = out + (size_t)b * (Dn * Nn) + (size_t)tid * Nn + n0;
        asm volatile("cp.async.bulk.global.shared::cta.bulk_group [%0], [%1], %2;"
                     :: "l"(dst), "r"(src), "r"(SL * 4) : "memory");
        asm volatile("cp.async.bulk.commit_group;" ::: "memory");
        asm volatile("cp.async.bulk.wait_group 0;" ::: "memory");
    }

    // no CTA may exit while peers can still read its DSMEM (zp)
    cluster_sync();
}

}  // namespace

extern "C" void kernel_launch(void* const* d_in, const int* in_sizes, int n_in,
                              void* d_out, int out_size) {
    const float* x = (const float*)d_in[0];
    const float* w = (const float*)d_in[1];
    if (n_in >= 2 && in_sizes[0] < in_sizes[1]) {
        const float* t = x; x = w; w = t;
    }
    cudaFuncSetAttribute(svpn_kernel, cudaFuncAttributeMaxDynamicSharedMemorySize,
                         SMEM_BYTES);
    svpn_kernel<<<Bn * CL, TPB, SMEM_BYTES>>>(x, w, (float*)d_out);
}

// round 13
// speedup vs baseline: 1.1130x; 1.1130x over previous
#include <cuda_runtime.h>
#include <cstdint>

namespace {

constexpr int Bn = 256, Dn = 256, Nn = 1024;
constexpr int CL = 8;          // cluster size (CTAs per batch)
constexpr int TPB = 1024;
constexpr int SL = 128;        // n-columns per CTA slice
constexpr float EPS_NORM = 1e-12f;
constexpr float EPS_DIV  = 1e-5f;

// dynamic smem layout (float offsets)
constexpr int OFF_XS  = 0;                    // 256*128 x-slice (32768)
constexpr int OFF_ZP  = 32768;                // 2 * 264 (z partial + 2 scalars, dbl buf)
constexpr int OFF_ZF  = OFF_ZP + 528;         // 260 allreduced z + scalars
constexpr int OFF_V   = OFF_ZF + 260;         // 256
constexpr int OFF_V1  = OFF_V + 256;          // 256
constexpr int OFF_U1  = OFF_V1 + 256;         // 128 (local slice)
constexpr int OFF_U2  = OFF_U1 + 128;         // 128
constexpr int OFF_WL  = OFF_U2 + 128;         // 128
constexpr int OFF_WP  = OFF_WL + 128;         // 16*128 w partials
constexpr int OFF_RED = OFF_WP + 2048;        // 64
constexpr int OFF_SS  = OFF_RED + 64;         // 2
constexpr int SMEM_BYTES = (OFF_SS + 4) * 4;  // ~143 KB

__device__ __forceinline__ unsigned cluster_rank() {
    unsigned r;
    asm("mov.u32 %0, %%cluster_ctarank;" : "=r"(r));
    return r;
}

__device__ __forceinline__ void cluster_sync() {
    asm volatile("barrier.cluster.arrive.aligned;" ::: "memory");
    asm volatile("barrier.cluster.wait.aligned;" ::: "memory");
}

__device__ __forceinline__ void cp16(void* dst_smem, const void* src) {
    unsigned d = (unsigned)__cvta_generic_to_shared(dst_smem);
    asm volatile("cp.async.cg.shared.global [%0], [%1], 16;" :: "r"(d), "l"(src));
}

// Block-wide sum over 1024 threads (32 warps). All threads must call.
__device__ __forceinline__ float block_reduce(float val, float* red) {
#pragma unroll
    for (int o = 16; o; o >>= 1) val += __shfl_down_sync(0xffffffffu, val, o);
    const int lane = threadIdx.x & 31;
    const int w    = threadIdx.x >> 5;
    if (lane == 0) red[w] = val;
    __syncthreads();
    if (w == 0) {
        val = red[lane];
#pragma unroll
        for (int o = 16; o; o >>= 1) val += __shfl_down_sync(0xffffffffu, val, o);
        if (lane == 0) red[0] = val;
    }
    __syncthreads();
    float r = red[0];
    __syncthreads();
    return r;
}

// Two simultaneous block-wide sums (one barrier trip for both).
__device__ __forceinline__ float2 block_reduce2(float a, float b, float* red) {
#pragma unroll
    for (int o = 16; o; o >>= 1) {
        a += __shfl_down_sync(0xffffffffu, a, o);
        b += __shfl_down_sync(0xffffffffu, b, o);
    }
    const int lane = threadIdx.x & 31;
    const int w    = threadIdx.x >> 5;
    if (lane == 0) { red[w] = a; red[32 + w] = b; }
    __syncthreads();
    if (w == 0) {
        a = red[lane];
        b = red[32 + lane];
#pragma unroll
        for (int o = 16; o; o >>= 1) {
            a += __shfl_down_sync(0xffffffffu, a, o);
            b += __shfl_down_sync(0xffffffffu, b, o);
        }
        if (lane == 0) { red[0] = a; red[32] = b; }
    }
    __syncthreads();
    float2 r = make_float2(red[0], red[32]);
    __syncthreads();
    return r;
}

__global__ __launch_bounds__(TPB, 1) __cluster_dims__(CL, 1, 1)
void svpn_kernel(const float* __restrict__ x,       // (B, D, N)
                 const float* __restrict__ weight,  // (D,)
                 float* __restrict__ out)           // (B, D*N)
{
    extern __shared__ float sm[];
    float* xs  = sm + OFF_XS;
    float* zp  = sm + OFF_ZP;
    float* zf  = sm + OFF_ZF;
    float* vv  = sm + OFF_V;
    float* v1  = sm + OFF_V1;
    float* u1l = sm + OFF_U1;
    float* u2l = sm + OFF_U2;
    float* wl  = sm + OFF_WL;
    float* wp  = sm + OFF_WP;
    float* red = sm + OFF_RED;
    float* sS  = sm + OFF_SS;

    const int tid = threadIdx.x;
    const unsigned rank = cluster_rank();   // 0..7
    const int b  = blockIdx.x / CL;
    const int n0 = (int)rank * SL;
    const float* xb = x + (size_t)b * (Dn * Nn);

    // ---- load x slice via cp.async.cg (8192 x 16B; warp == one 512B row) ----
#pragma unroll
    for (int k = 0; k < 8; ++k) {
        const int id = tid + k * TPB;
        const int d  = id >> 5, c4 = id & 31;
        cp16(xs + d * SL + c4 * 4, xb + (size_t)d * Nn + n0 + c4 * 4);
    }
    asm volatile("cp.async.commit_group;" ::: "memory");
    if (tid < Dn) vv[tid] = weight[tid];
    asm volatile("cp.async.wait_group 0;" ::: "memory");
    __syncthreads();

    const int g    = tid >> 6;   // 0..15 : d-group of 16 rows (w-phase)
    const int p    = tid & 63;   // float2 column index      (w-phase)
    const int wid_ = tid >> 5, lane = tid & 31;
    const float2* xs2 = reinterpret_cast<const float2*>(xs);
    const float4* xs4 = reinterpret_cast<const float4*>(xs);
    const float4* wl4 = reinterpret_cast<const float4*>(wl);
    float2* wp2 = reinterpret_cast<float2*>(wp);

    float s1  = 0.f;
    float c_u = 0.f;   // s1 * (v1 . v), maintained incrementally

    for (int sv = 0; sv < 2; ++sv) {
        for (int it = 0; it < 3; ++it) {
            const int buf = (((sv * 3 + it) & 1) ? 264 : 0);

            // ---- w-phase: partial w over 16 d's per group (float2 columns) ----
            float vreg[16];
#pragma unroll
            for (int i = 0; i < 16; ++i) vreg[i] = vv[g * 16 + i];
            float2 acc = make_float2(0.f, 0.f);
#pragma unroll
            for (int i = 0; i < 16; ++i) {
                float2 xv = xs2[(g * 16 + i) * 64 + p];
                acc.x = fmaf(xv.x, vreg[i], acc.x);
                acc.y = fmaf(xv.y, vreg[i], acc.y);
            }
            wp2[g * 64 + p] = acc;
            __syncthreads();

            // ---- w reduce over the 16 groups + u-side deflation ----
            if (tid < SL) {
                float w = 0.f;
#pragma unroll
                for (int gg = 0; gg < 16; ++gg) w += wp[gg * SL + tid];
                if (sv) w -= c_u * u1l[tid];
                wl[tid] = w;
            }
            __syncthreads();

            // ---- local scalar partials: ||w||^2 , u1.w  (one barrier trip) ----
            float wv_ = (tid < SL) ? wl[tid] : 0.f;
            float u1w = (sv && tid < SL) ? u1l[tid] * wv_ : 0.f;
            float2 sc = block_reduce2(wv_ * wv_, u1w, red);

            // ---- z partials: warp per row, float4, shuffle reduce ----
#pragma unroll
            for (int k = 0; k < 8; ++k) {
                const int d = wid_ * 8 + k;
                float4 xv  = xs4[d * 32 + lane];
                float4 wv4 = wl4[lane];
                float r_ = fmaf(xv.x, wv4.x,
                           fmaf(xv.y, wv4.y,
                           fmaf(xv.z, wv4.z, xv.w * wv4.w)));
#pragma unroll
                for (int o = 16; o; o >>= 1)
                    r_ += __shfl_down_sync(0xffffffffu, r_, o);
                if (lane == 0) zp[buf + d] = r_;
            }
            if (tid == 0) { zp[buf + 256] = sc.x; zp[buf + 257] = sc.y; }

            cluster_sync();

            // ---- DSMEM allreduce of 258 floats across the 8 CTAs ----
            if (tid < 258) {
                unsigned base =
                    (unsigned)__cvta_generic_to_shared(zp + buf) + (unsigned)tid * 4u;
                float a = 0.f;
#pragma unroll
                for (int r = 0; r < CL; ++r) {
                    unsigned pa;
                    asm("mapa.shared::cluster.u32 %0, %1, %2;"
                        : "=r"(pa) : "r"(base), "r"(r));
                    float v_;
                    asm("ld.shared::cluster.f32 %0, [%1];" : "=f"(v_) : "r"(pa));
                    a += v_;
                }
                zf[tid] = a;
            }
            __syncthreads();

            const float sw2  = zf[256];
            const float su1w = zf[257];
            float zd = 0.f;
            if (tid < Dn) {
                zd = zf[tid];
                if (sv) zd -= s1 * su1w * v1[tid];   // z-side deflation
            }
            // ||z||^2 and v1.z in one barrier trip
            float2 zr = block_reduce2((tid < Dn) ? zd * zd : 0.f,
                                      (tid < Dn) ? v1[tid] * zd : 0.f, red);
            const float nz  = sqrtf(zr.x);
            const float nzc = fmaxf(nz, EPS_NORM);
            if (tid < Dn) vv[tid] = zd / nzc;
            c_u = s1 * (zr.y / nzc);                 // s1*(v1 . v_new) for next iter

            if (it == 2) {
                const float nw   = fmaxf(sqrtf(sw2), EPS_NORM);
                const float invw = 1.f / nw;
                const float sval = nz / nw;          // s = ||A^T u||
                if (sv == 0) {
                    if (tid < SL) u1l[tid] = wl[tid] * invw;
                    if (tid < Dn) v1[tid]  = zd / nzc;
                    if (tid == 0) sS[0] = sval;
                } else {
                    if (tid < SL) u2l[tid] = wl[tid] * invw;
                    if (tid == 0) sS[1] = sval;
                }
            }
            __syncthreads();
        }
        if (sv == 0) {
            s1 = sS[0];
            if (tid < Dn) vv[tid] = weight[tid];
            __syncthreads();
            // c_u for the first iteration of component 2: s1 * (v1 . weight)
            float pr = (tid < Dn) ? v1[tid] * vv[tid] : 0.f;
            c_u = s1 * block_reduce(pr, red);
        }
    }

    // ---- epilogue: out = c*x + c1*u1 v1^T + c2*u2 v2^T  (smem -> STG.128) ----
    const float s1f = sS[0], s2f = sS[1];
    const float c  = 1.f / (sqrtf(s2f) + EPS_DIV);
    const float c1 = sqrtf(s1f) - s1f * c;
    const float c2 = sqrtf(s2f) - s2f * c;

    const float4* u14 = reinterpret_cast<const float4*>(u1l);
    const float4* u24 = reinterpret_cast<const float4*>(u2l);
    float4* ob4 = reinterpret_cast<float4*>(out + (size_t)b * (Dn * Nn) + n0);

#pragma unroll
    for (int k = 0; k < 8; ++k) {
        const int idx  = tid + k * TPB;   // 0..8191 (256 rows x 32 float4)
        const int d    = idx >> 5;
        const int col4 = idx & 31;
        const float a1 = c1 * v1[d];
        const float a2 = c2 * vv[d];      // vv holds v2
        float4 xv = xs4[idx];
        float4 uA = u14[col4];
        float4 uB = u24[col4];
        float4 o;
        o.x = fmaf(c, xv.x, fmaf(a1, uA.x, a2 * uB.x));
        o.y = fmaf(c, xv.y, fmaf(a1, uA.y, a2 * uB.y));
        o.z = fmaf(c, xv.z, fmaf(a1, uA.z, a2 * uB.z));
        o.w = fmaf(c, xv.w, fmaf(a1, uA.w, a2 * uB.w));
        __stcs(&ob4[(size_t)d * (Nn / 4) + col4], o);
    }

    // no CTA may exit while peers can still read its DSMEM (zp)
    cluster_sync();
}

}  // namespace

extern "C" void kernel_launch(void* const* d_in, const int* in_sizes, int n_in,
                              void* d_out, int out_size) {
    const float* x = (const float*)d_in[0];
    const float* w = (const float*)d_in[1];
    if (n_in >= 2 && in_sizes[0] < in_sizes[1]) {
        const float* t = x; x = w; w = t;
    }
    cudaFuncSetAttribute(svpn_kernel, cudaFuncAttributeMaxDynamicSharedMemorySize,
                         SMEM_BYTES);
    svpn_kernel<<<Bn * CL, TPB, SMEM_BYTES>>>(x, w, (float*)d_out);
}

// round 14
// speedup vs baseline: 1.3338x; 1.1984x over previous
#include <cuda_runtime.h>
#include <cstdint>

namespace {

constexpr int Bn = 256, Dn = 256, Nn = 1024;
constexpr int TPB = 1024, GRID = 96;
constexpr int TS = 64, NT = Nn / TS;          // 16 tiles of 64 columns
constexpr float EPS_NORM = 1e-12f;
constexpr float EPS_DIV  = 1e-5f;

// dynamic smem layout (float offsets)
constexpr int OFF_ZSC   = 0;                  // 256 rows x 68 (padded) = 17408
constexpr int OFF_ZRB   = 17408;              // 1024
constexpr int OFF_WPART = OFF_ZRB + 1024;     // 1024
constexpr int OFF_UCUR  = OFF_WPART + 1024;   // 1024
constexpr int OFF_U1    = OFF_UCUR + 1024;    // 1024
constexpr int OFF_VV    = OFF_U1 + 1024;      // 256
constexpr int OFF_V1    = OFF_VV + 256;       // 256
constexpr int OFF_WS    = OFF_V1 + 256;       // 64
constexpr int OFF_RED   = OFF_WS + 64;        // 64
constexpr int OFF_SS    = OFF_RED + 64;       // 4
constexpr int SMEM_FLOATS = OFF_SS + 4;
constexpr int SMEM_BYTES  = SMEM_FLOATS * 4;  // ~88.7 KB

// Block-wide sum over 1024 threads (32 warps). All threads must call.
__device__ __forceinline__ float block_reduce(float val, float* red) {
#pragma unroll
    for (int o = 16; o; o >>= 1) val += __shfl_down_sync(0xffffffffu, val, o);
    const int lane = threadIdx.x & 31;
    const int w    = threadIdx.x >> 5;
    if (lane == 0) red[w] = val;
    __syncthreads();
    if (w == 0) {
        val = red[lane];
#pragma unroll
        for (int o = 16; o; o >>= 1) val += __shfl_down_sync(0xffffffffu, val, o);
        if (lane == 0) red[0] = val;
    }
    __syncthreads();
    float r = red[0];
    __syncthreads();
    return r;
}

// Two simultaneous block-wide sums (one barrier trip for both).
__device__ __forceinline__ float2 block_reduce2(float a, float b, float* red) {
#pragma unroll
    for (int o = 16; o; o >>= 1) {
        a += __shfl_down_sync(0xffffffffu, a, o);
        b += __shfl_down_sync(0xffffffffu, b, o);
    }
    const int lane = threadIdx.x & 31;
    const int w    = threadIdx.x >> 5;
    if (lane == 0) { red[w] = a; red[32 + w] = b; }
    __syncthreads();
    if (w == 0) {
        a = red[lane];
        b = red[32 + lane];
#pragma unroll
        for (int o = 16; o; o >>= 1) {
            a += __shfl_down_sync(0xffffffffu, a, o);
            b += __shfl_down_sync(0xffffffffu, b, o);
        }
        if (lane == 0) { red[0] = a; red[32] = b; }
    }
    __syncthreads();
    float2 r = make_float2(red[0], red[32]);
    __syncthreads();
    return r;
}

__global__ __launch_bounds__(TPB, 1) void svpn_kernel(
    const float* __restrict__ x,       // (B, D, N)
    const float* __restrict__ weight,  // (D,)
    float* __restrict__ out)           // (B, D*N)
{
    extern __shared__ float sm[];
    float* zsc   = sm + OFF_ZSC;
    float* zrb   = sm + OFF_ZRB;
    float* wpart = sm + OFF_WPART;
    float* ucur  = sm + OFF_UCUR;   // unnormalized w of current pass (ends as u2)
    float* u1    = sm + OFF_U1;     // normalized u of component 1
    float* vv    = sm + OFF_VV;
    float* v1    = sm + OFF_V1;
    float* ws    = sm + OFF_WS;
    float* red   = sm + OFF_RED;
    float* sS    = sm + OFF_SS;

    const int tid = threadIdx.x;
    const int g   = tid >> 6;     // 0..15 : 16-row strip
    const int n_w = tid & 63;     // column within tile

    for (int b = blockIdx.x; b < Bn; b += GRID) {
        const float* xb = x + (size_t)b * (Dn * Nn);
        if (tid < Dn) vv[tid] = weight[tid];
        __syncthreads();

        float s1 = 0.f, c_u = 0.f;

        for (int sv = 0; sv < 2; ++sv) {
            for (int it = 0; it < 3; ++it) {
                float zpart[16];
#pragma unroll
                for (int i = 0; i < 16; ++i) zpart[i] = 0.f;

                // load strip for tile 0 (16 independent LDGs, coalesced across lanes)
                float xreg[16];
                {
                    const float* p = xb + n_w;
#pragma unroll
                    for (int i = 0; i < 16; ++i)
                        xreg[i] = p[(size_t)(g * 16 + i) * Nn];
                }

                for (int t = 0; t < NT; ++t) {
                    // w partial: strip-dot against v (v via LDS broadcast)
                    float wp = 0.f;
#pragma unroll
                    for (int i = 0; i < 16; ++i)
                        wp = fmaf(xreg[i], vv[g * 16 + i], wp);
                    wpart[tid] = wp;
                    __syncthreads();

                    // reduce 16 strips -> ws (64 cols) + u-side deflation
                    if (tid < TS) {
                        float wsum = 0.f;
#pragma unroll
                        for (int gg = 0; gg < 16; ++gg) wsum += wpart[gg * 64 + tid];
                        if (sv) wsum -= c_u * u1[t * TS + tid];
                        ws[tid] = wsum;
                        ucur[t * TS + tid] = wsum;
                    }
                    __syncthreads();

                    // z partials in registers (no smem re-read of x)
                    const float wsv = ws[n_w];
#pragma unroll
                    for (int i = 0; i < 16; ++i)
                        zpart[i] = fmaf(xreg[i], wsv, zpart[i]);

                    // prefetch next tile's strip
                    if (t + 1 < NT) {
                        const float* p = xb + (t + 1) * TS + n_w;
#pragma unroll
                        for (int i = 0; i < 16; ++i)
                            xreg[i] = p[(size_t)(g * 16 + i) * Nn];
                    }
                }  // tiles

                // scalar partials over the full (unnormalized) w
                float wv_ = ucur[tid];
                float2 sc = block_reduce2(wv_ * wv_,
                                          sv ? u1[tid] * wv_ : 0.f, red);

                // z reduction: zsc[d][n_w] (padded 68) -> 4 partials -> zb
#pragma unroll
                for (int i = 0; i < 16; ++i)
                    zsc[(g * 16 + i) * 68 + n_w] = zpart[i];
                __syncthreads();
                {
                    const int d = tid & 255, q = tid >> 8;
                    const float4* z4 = reinterpret_cast<const float4*>(zsc);
                    float s = 0.f;
#pragma unroll
                    for (int j = 0; j < 4; ++j) {
                        float4 a = z4[d * 17 + q * 4 + j];
                        s += a.x + a.y + a.z + a.w;
                    }
                    zrb[q * 256 + d] = s;
                }
                __syncthreads();

                float zd = 0.f;
                if (tid < Dn) {
                    zd = zrb[tid] + zrb[256 + tid] + zrb[512 + tid] + zrb[768 + tid];
                    if (sv) zd -= s1 * sc.y * v1[tid];   // z-side deflation
                }
                float2 zr = block_reduce2((tid < Dn) ? zd * zd : 0.f,
                                          (tid < Dn) ? v1[tid] * zd : 0.f, red);
                const float nz  = sqrtf(zr.x);
                const float nzc = fmaxf(nz, EPS_NORM);
                if (tid < Dn) vv[tid] = zd / nzc;
                c_u = s1 * (zr.y / nzc);                 // s1*(v1 . v_new)

                if (it == 2) {
                    const float nw_  = fmaxf(sqrtf(sc.x), EPS_NORM);
                    const float invw = 1.f / nw_;
                    const float sval = nz / nw_;         // s = ||A^T u||
                    if (sv == 0) {
                        u1[tid] = ucur[tid] * invw;
                        if (tid < Dn) v1[tid] = zd / nzc;
                        if (tid == 0) sS[0] = sval;
                    } else {
                        ucur[tid] *= invw;               // ucur becomes u2
                        if (tid == 0) sS[1] = sval;
                    }
                }
                __syncthreads();
            }  // it

            if (sv == 0) {
                s1 = sS[0];
                if (tid < Dn) vv[tid] = weight[tid];
                __syncthreads();
                float pr = (tid < Dn) ? v1[tid] * vv[tid] : 0.f;
                c_u = s1 * block_reduce(pr, red);
            }
        }  // sv

        // epilogue: out = c*x + c1*u1 v1^T + c2*u2 v2^T
        const float s1f = sS[0], s2f = sS[1];
        const float c  = 1.f / (sqrtf(s2f) + EPS_DIV);
        const float c1 = sqrtf(s1f) - s1f * c;
        const float c2 = sqrtf(s2f) - s2f * c;

        const float4* x4  = reinterpret_cast<const float4*>(xb);
        float4*       o4  = reinterpret_cast<float4*>(out + (size_t)b * (Dn * Nn));
        const float4* u14 = reinterpret_cast<const float4*>(u1);
        const float4* u24 = reinterpret_cast<const float4*>(ucur);  // u2

        constexpr int TOT4 = Dn * Nn / 4;  // 65536
#pragma unroll 4
        for (int idx = tid; idx < TOT4; idx += TPB) {
            const int d   = idx >> 8;
            const int col = idx & 255;
            const float a1 = c1 * v1[d];
            const float a2 = c2 * vv[d];   // vv holds v2
            const float4 xv = __ldcs(&x4[idx]);
            const float4 uA = u14[col];
            const float4 uB = u24[col];
            float4 o;
            o.x = fmaf(c, xv.x, fmaf(a1, uA.x, a2 * uB.x));
            o.y = fmaf(c, xv.y, fmaf(a1, uA.y, a2 * uB.y));
            o.z = fmaf(c, xv.z, fmaf(a1, uA.z, a2 * uB.z));
            o.w = fmaf(c, xv.w, fmaf(a1, uA.w, a2 * uB.w));
            __stcs(&o4[idx], o);
        }
        __syncthreads();  // protect smem before next batch
    }  // batch loop
}

}  // namespace

extern "C" void kernel_launch(void* const* d_in, const int* in_sizes, int n_in,
                              void* d_out, int out_size) {
    const float* x = (const float*)d_in[0];
    const float* w = (const float*)d_in[1];
    if (n_in >= 2 && in_sizes[0] < in_sizes[1]) {
        const float* t = x; x = w; w = t;
    }
    cudaFuncSetAttribute(svpn_kernel, cudaFuncAttributeMaxDynamicSharedMemorySize,
                         SMEM_BYTES);
    svpn_kernel<<<GRID, TPB, SMEM_BYTES>>>(x, w, (float*)d_out);
}

// round 15
// speedup vs baseline: 1.6029x; 1.2018x over previous
#include <cuda_runtime.h>
#include <cstdint>

namespace {

constexpr int Bn = 256, Dn = 256, Nn = 1024;
constexpr int TPB = 1024, GRID = 128;
constexpr int TS = 64, NT = Nn / TS;          // 16 tiles of 64 columns
constexpr float EPS_NORM = 1e-12f;
constexpr float EPS_DIV  = 1e-5f;

// dynamic smem layout (float offsets)
constexpr int OFF_WPART = 0;                  // 64 groups x 64 cols = 4096
constexpr int OFF_ZSC   = 4096;               // 256 rows x 17 (padded) = 4352
constexpr int OFF_UCUR  = OFF_ZSC + 4352;     // 1024
constexpr int OFF_U1    = OFF_UCUR + 1024;    // 1024
constexpr int OFF_VV    = OFF_U1 + 1024;      // 256
constexpr int OFF_V1    = OFF_VV + 256;       // 256
constexpr int OFF_WS    = OFF_V1 + 256;       // 64
constexpr int OFF_RED   = OFF_WS + 64;        // 64
constexpr int OFF_SS    = OFF_RED + 64;       // 4
constexpr int SMEM_BYTES = (OFF_SS + 4) * 4;  // ~44.5 KB

// Block-wide sum over 1024 threads (32 warps). All threads must call.
__device__ __forceinline__ float block_reduce(float val, float* red) {
#pragma unroll
    for (int o = 16; o; o >>= 1) val += __shfl_down_sync(0xffffffffu, val, o);
    const int lane = threadIdx.x & 31;
    const int w    = threadIdx.x >> 5;
    if (lane == 0) red[w] = val;
    __syncthreads();
    if (w == 0) {
        val = red[lane];
#pragma unroll
        for (int o = 16; o; o >>= 1) val += __shfl_down_sync(0xffffffffu, val, o);
        if (lane == 0) red[0] = val;
    }
    __syncthreads();
    float r = red[0];
    __syncthreads();
    return r;
}

// Two simultaneous block-wide sums (one barrier trip for both).
__device__ __forceinline__ float2 block_reduce2(float a, float b, float* red) {
#pragma unroll
    for (int o = 16; o; o >>= 1) {
        a += __shfl_down_sync(0xffffffffu, a, o);
        b += __shfl_down_sync(0xffffffffu, b, o);
    }
    const int lane = threadIdx.x & 31;
    const int w    = threadIdx.x >> 5;
    if (lane == 0) { red[w] = a; red[32 + w] = b; }
    __syncthreads();
    if (w == 0) {
        a = red[lane];
        b = red[32 + lane];
#pragma unroll
        for (int o = 16; o; o >>= 1) {
            a += __shfl_down_sync(0xffffffffu, a, o);
            b += __shfl_down_sync(0xffffffffu, b, o);
        }
        if (lane == 0) { red[0] = a; red[32] = b; }
    }
    __syncthreads();
    float2 r = make_float2(red[0], red[32]);
    __syncthreads();
    return r;
}

__global__ __launch_bounds__(TPB, 1) void svpn_kernel(
    const float* __restrict__ x,       // (B, D, N)
    const float* __restrict__ weight,  // (D,)
    float* __restrict__ out)           // (B, D*N)
{
    extern __shared__ float sm[];
    float* wpart = sm + OFF_WPART;
    float* zsc   = sm + OFF_ZSC;
    float* ucur  = sm + OFF_UCUR;   // unnormalized w of current pass (ends as u2)
    float* u1    = sm + OFF_U1;     // normalized u of component 1
    float* vv    = sm + OFF_VV;
    float* v1    = sm + OFF_V1;
    float* ws    = sm + OFF_WS;
    float* red   = sm + OFF_RED;
    float* sS    = sm + OFF_SS;

    const int tid = threadIdx.x;
    const int q4  = tid & 15;       // column quad: cols 4*q4 .. 4*q4+3 within tile
    const int g4  = (tid >> 4) * 4; // row base: rows g4 .. g4+3

    for (int b = blockIdx.x; b < Bn; b += GRID) {
        const float* xb = x + (size_t)b * (Dn * Nn);
        const float4* xb4 = reinterpret_cast<const float4*>(xb);
        if (tid < Dn) vv[tid] = weight[tid];
        __syncthreads();

        float s1 = 0.f, c_u = 0.f;

        for (int sv = 0; sv < 2; ++sv) {
            for (int it = 0; it < 3; ++it) {
                float zpart[4];
#pragma unroll
                for (int i = 0; i < 4; ++i) zpart[i] = 0.f;

                float4 xA[4], xB[4];
                // load tile 0 strip
#pragma unroll
                for (int i = 0; i < 4; ++i)
                    xA[i] = xb4[(size_t)(g4 + i) * (Nn / 4) + q4];

                // tile body: prefetch t+1 into nxt, compute on cur
                auto tile_body = [&](int t, float4 (&cur)[4], float4 (&nxt)[4]) {
                    if (t + 1 < NT) {
#pragma unroll
                        for (int i = 0; i < 4; ++i)
                            nxt[i] = xb4[(size_t)(g4 + i) * (Nn / 4)
                                         + (t + 1) * (TS / 4) + q4];
                    }
                    // w-phase: per-column partials over this thread's 4 rows
                    float4 wp = make_float4(0.f, 0.f, 0.f, 0.f);
#pragma unroll
                    for (int i = 0; i < 4; ++i) {
                        const float vvi = vv[g4 + i];
                        wp.x = fmaf(cur[i].x, vvi, wp.x);
                        wp.y = fmaf(cur[i].y, vvi, wp.y);
                        wp.z = fmaf(cur[i].z, vvi, wp.z);
                        wp.w = fmaf(cur[i].w, vvi, wp.w);
                    }
                    *reinterpret_cast<float4*>(&wpart[tid << 2]) = wp;
                    __syncthreads();

                    // reduce 64 groups -> ws (64 cols) + u-side deflation
                    if (tid < TS) {
                        float a0 = 0.f, a1 = 0.f, a2 = 0.f, a3 = 0.f;
#pragma unroll
                        for (int gg = 0; gg < 64; gg += 4) {
                            a0 += wpart[(gg + 0) * 64 + tid];
                            a1 += wpart[(gg + 1) * 64 + tid];
                            a2 += wpart[(gg + 2) * 64 + tid];
                            a3 += wpart[(gg + 3) * 64 + tid];
                        }
                        float wsum = (a0 + a1) + (a2 + a3);
                        if (sv) wsum -= c_u * u1[t * TS + tid];
                        ws[tid] = wsum;
                        ucur[t * TS + tid] = wsum;
                    }
                    __syncthreads();

                    // z-phase: accumulate row dots in registers
                    const float4 wv4 =
                        *reinterpret_cast<const float4*>(&ws[q4 << 2]);
#pragma unroll
                    for (int i = 0; i < 4; ++i)
                        zpart[i] = fmaf(cur[i].x, wv4.x,
                                   fmaf(cur[i].y, wv4.y,
                                   fmaf(cur[i].z, wv4.z,
                                   fmaf(cur[i].w, wv4.w, zpart[i]))));
                };

                for (int tt = 0; tt < NT / 2; ++tt) {
                    tile_body(2 * tt,     xA, xB);
                    tile_body(2 * tt + 1, xB, xA);
                }

                // dump z partials: row r = g4+i, column-quad q4
#pragma unroll
                for (int i = 0; i < 4; ++i)
                    zsc[(g4 + i) * 17 + q4] = zpart[i];

                // scalar partials: ||w||^2 , u1.w  (one barrier trip; also
                // makes zsc writes visible)
                float wv_ = ucur[tid];
                float2 sc = block_reduce2(wv_ * wv_,
                                          sv ? u1[tid] * wv_ : 0.f, red);

                float zd = 0.f;
                if (tid < Dn) {
                    float a0 = 0.f, a1 = 0.f;
#pragma unroll
                    for (int q = 0; q < 16; q += 2) {
                        a0 += zsc[tid * 17 + q];
                        a1 += zsc[tid * 17 + q + 1];
                    }
                    zd = a0 + a1;
                    if (sv) zd -= s1 * sc.y * v1[tid];   // z-side deflation
                }
                float2 zr = block_reduce2((tid < Dn) ? zd * zd : 0.f,
                                          (tid < Dn) ? v1[tid] * zd : 0.f, red);
                const float nz  = sqrtf(zr.x);
                const float nzc = fmaxf(nz, EPS_NORM);
                if (tid < Dn) vv[tid] = zd / nzc;
                c_u = s1 * (zr.y / nzc);                 // s1*(v1 . v_new)

                if (it == 2) {
                    const float nw_  = fmaxf(sqrtf(sc.x), EPS_NORM);
                    const float invw = 1.f / nw_;
                    const float sval = nz / nw_;         // s = ||A^T u||
                    if (sv == 0) {
                        u1[tid] = ucur[tid] * invw;
                        if (tid < Dn) v1[tid] = zd / nzc;
                        if (tid == 0) sS[0] = sval;
                    } else {
                        ucur[tid] *= invw;               // ucur becomes u2
                        if (tid == 0) sS[1] = sval;
                    }
                }
                __syncthreads();
            }  // it

            if (sv == 0) {
                s1 = sS[0];
                if (tid < Dn) vv[tid] = weight[tid];
                __syncthreads();
                float pr = (tid < Dn) ? v1[tid] * vv[tid] : 0.f;
                c_u = s1 * block_reduce(pr, red);
            }
        }  // sv

        // epilogue: out = c*x + c1*u1 v1^T + c2*u2 v2^T
        const float s1f = sS[0], s2f = sS[1];
        const float c  = 1.f / (sqrtf(s2f) + EPS_DIV);
        const float c1 = sqrtf(s1f) - s1f * c;
        const float c2 = sqrtf(s2f) - s2f * c;

        float4*       o4  = reinterpret_cast<float4*>(out + (size_t)b * (Dn * Nn));
        const float4* u14 = reinterpret_cast<const float4*>(u1);
        const float4* u24 = reinterpret_cast<const float4*>(ucur);  // u2

        constexpr int TOT4 = Dn * Nn / 4;  // 65536
#pragma unroll 4
        for (int idx = tid; idx < TOT4; idx += TPB) {
            const int d   = idx >> 8;
            const int col = idx & 255;
            const float a1 = c1 * v1[d];
            const float a2 = c2 * vv[d];   // vv holds v2
            const float4 xv = __ldcs(&xb4[idx]);
            const float4 uA = u14[col];
            const float4 uB = u24[col];
            float4 o;
            o.x = fmaf(c, xv.x, fmaf(a1, uA.x, a2 * uB.x));
            o.y = fmaf(c, xv.y, fmaf(a1, uA.y, a2 * uB.y));
            o.z = fmaf(c, xv.z, fmaf(a1, uA.z, a2 * uB.z));
            o.w = fmaf(c, xv.w, fmaf(a1, uA.w, a2 * uB.w));
            __stcs(&o4[idx], o);
        }
        __syncthreads();  // protect smem before next batch
    }  // batch loop
}

}  // namespace

extern "C" void kernel_launch(void* const* d_in, const int* in_sizes, int n_in,
                              void* d_out, int out_size) {
    const float* x = (const float*)d_in[0];
    const float* w = (const float*)d_in[1];
    if (n_in >= 2 && in_sizes[0] < in_sizes[1]) {
        const float* t = x; x = w; w = t;
    }
    cudaFuncSetAttribute(svpn_kernel, cudaFuncAttributeMaxDynamicSharedMemorySize,
                         SMEM_BYTES);
    svpn_kernel<<<GRID, TPB, SMEM_BYTES>>>(x, w, (float*)d_out);
}